// round 7
// baseline (speedup 1.0000x reference)
#include <cuda_runtime.h>
#include <cuda_fp16.h>

#define N_NODES 50000
#define N_PAD   50176            // 49 * 1024
#define IN_CH   128
#define HEADS   4
#define OUT_CH  32
#define FEAT    128
#define NEG_SLOPE 0.2f
#define SCAN_NB 49
#define MAX_E   800000

// ---------------- scratch (static device globals: allocation-free) -----------
__device__ __align__(16) __half g_feat_h[N_NODES * FEAT];  // fp16 features [n][h*32+d]
__device__ __align__(16) float  g_el[N_NODES * HEADS];
__device__ __align__(16) float  g_er[N_NODES * HEADS];
// g_deg[N_PAD] = degree counters; g_deg[N_PAD] = scan arrival counter.
// The memset covers N_PAD+4 ints so the barrier resets on every graph replay.
__device__ __align__(16) int    g_deg[N_PAD + 4];
__device__ __align__(16) int    g_off[N_PAD + 16];
__device__ volatile int g_bsum[SCAN_NB];
__device__ __align__(16) int    g_csr[MAX_E];
__device__ __align__(16) int    g_rank[MAX_E];             // edge rank within its dst bucket

// ---------------- side stream + events for forked capture --------------------
static cudaStream_t g_s2;
static cudaEvent_t  g_ev_fork, g_ev_join;
static struct StreamInit {
    StreamInit() {
        cudaStreamCreateWithFlags(&g_s2, cudaStreamNonBlocking);
        cudaEventCreateWithFlags(&g_ev_fork, cudaEventDisableTiming);
        cudaEventCreateWithFlags(&g_ev_join, cudaEventDisableTiming);
    }
} g_stream_init;

__device__ __forceinline__ unsigned f2tf32(float f) {
    unsigned o;
    asm("cvt.rna.tf32.f32 %0, %1;" : "=r"(o) : "f"(f));
    return o;
}

// ---------------- 1) feat = x @ W via tf32 mma + fused el/er epilogue --------
#define XS_STRIDE 36
#define WS_STRIDE 136

__global__ __launch_bounds__(256) void gemm_kernel(const float* __restrict__ x,
                                                   const float* __restrict__ W,
                                                   const float* __restrict__ attn_l,
                                                   const float* __restrict__ attn_r) {
    __shared__ unsigned xs[128 * XS_STRIDE];
    __shared__ unsigned ws[32 * WS_STRIDE];
    __shared__ float    s_attn[256];

    const int t      = threadIdx.x;
    const int lane   = t & 31;
    const int wid    = t >> 5;
    const int warp_m = wid & 3;
    const int warp_n = wid >> 2;
    const int g      = lane >> 2;
    const int c      = lane & 3;
    const int rbase  = blockIdx.x * 128;

    s_attn[t] = (t < 128) ? attn_l[t] : attn_r[t - 128];

    float d[2][8][4];
    #pragma unroll
    for (int mt = 0; mt < 2; mt++)
        #pragma unroll
        for (int nt = 0; nt < 8; nt++)
            #pragma unroll
            for (int q = 0; q < 4; q++) d[mt][nt][q] = 0.f;

    for (int kk = 0; kk < IN_CH; kk += 32) {
        #pragma unroll
        for (int p = 0; p < 4; p++) {
            int idx = p * 256 + t;
            int r = idx >> 3, c4 = idx & 7;
            int row = rbase + r;
            float4 xv = make_float4(0.f, 0.f, 0.f, 0.f);
            if (row < N_NODES) xv = *(const float4*)(x + row * IN_CH + kk + c4 * 4);
            unsigned* dptr = xs + r * XS_STRIDE + c4 * 4;
            dptr[0] = f2tf32(xv.x); dptr[1] = f2tf32(xv.y);
            dptr[2] = f2tf32(xv.z); dptr[3] = f2tf32(xv.w);
        }
        #pragma unroll
        for (int p = 0; p < 4; p++) {
            int idx = p * 256 + t;
            int k = idx >> 5, n4 = idx & 31;
            float4 wv = *(const float4*)(W + (kk + k) * FEAT + n4 * 4);
            unsigned* dptr = ws + k * WS_STRIDE + n4 * 4;
            dptr[0] = f2tf32(wv.x); dptr[1] = f2tf32(wv.y);
            dptr[2] = f2tf32(wv.z); dptr[3] = f2tf32(wv.w);
        }
        __syncthreads();

        #pragma unroll
        for (int k0 = 0; k0 < 32; k0 += 8) {
            unsigned a[2][4];
            #pragma unroll
            for (int mt = 0; mt < 2; mt++) {
                int r0 = (warp_m * 32 + mt * 16 + g) * XS_STRIDE + k0 + c;
                int r1 = r0 + 8 * XS_STRIDE;
                a[mt][0] = xs[r0];     a[mt][1] = xs[r1];
                a[mt][2] = xs[r0 + 4]; a[mt][3] = xs[r1 + 4];
            }
            #pragma unroll
            for (int nt = 0; nt < 8; nt++) {
                int coln = warp_n * 64 + nt * 8 + g;
                unsigned b0 = ws[(k0 + c) * WS_STRIDE + coln];
                unsigned b1 = ws[(k0 + c + 4) * WS_STRIDE + coln];
                #pragma unroll
                for (int mt = 0; mt < 2; mt++) {
                    asm volatile(
                        "mma.sync.aligned.m16n8k8.row.col.f32.tf32.tf32.f32 "
                        "{%0,%1,%2,%3}, {%4,%5,%6,%7}, {%8,%9}, {%0,%1,%2,%3};"
                        : "+f"(d[mt][nt][0]), "+f"(d[mt][nt][1]),
                          "+f"(d[mt][nt][2]), "+f"(d[mt][nt][3])
                        : "r"(a[mt][0]), "r"(a[mt][1]), "r"(a[mt][2]), "r"(a[mt][3]),
                          "r"(b0), "r"(b1));
                }
            }
        }
        __syncthreads();
    }

    const int h0 = warp_n * 2;
    float al[2][8], ar[2][8];
    #pragma unroll
    for (int q = 0; q < 2; q++)
        #pragma unroll
        for (int i = 0; i < 8; i++) {
            int col = (i >> 1) * 8 + c * 2 + (i & 1);
            al[q][i] = s_attn[(h0 + q) * OUT_CH + col];
            ar[q][i] = s_attn[128 + (h0 + q) * OUT_CH + col];
        }

    #pragma unroll
    for (int mt = 0; mt < 2; mt++) {
        #pragma unroll
        for (int v = 0; v < 2; v++) {
            int row = rbase + warp_m * 32 + mt * 16 + g + v * 8;

            float pl0 = 0.f, pr0 = 0.f, pl1 = 0.f, pr1 = 0.f;
            #pragma unroll
            for (int nt = 0; nt < 4; nt++) {
                float v0 = d[mt][nt][v * 2], v1 = d[mt][nt][v * 2 + 1];
                pl0 += v0 * al[0][nt * 2] + v1 * al[0][nt * 2 + 1];
                pr0 += v0 * ar[0][nt * 2] + v1 * ar[0][nt * 2 + 1];
            }
            #pragma unroll
            for (int nt = 4; nt < 8; nt++) {
                float v0 = d[mt][nt][v * 2], v1 = d[mt][nt][v * 2 + 1];
                pl1 += v0 * al[1][(nt - 4) * 2] + v1 * al[1][(nt - 4) * 2 + 1];
                pr1 += v0 * ar[1][(nt - 4) * 2] + v1 * ar[1][(nt - 4) * 2 + 1];
            }
            #pragma unroll
            for (int s = 1; s < 4; s <<= 1) {
                pl0 += __shfl_xor_sync(0xffffffffu, pl0, s, 4);
                pr0 += __shfl_xor_sync(0xffffffffu, pr0, s, 4);
                pl1 += __shfl_xor_sync(0xffffffffu, pl1, s, 4);
                pr1 += __shfl_xor_sync(0xffffffffu, pr1, s, 4);
            }

            if (row < N_NODES) {
                if (c == 0) {
                    g_el[row * HEADS + h0]     = pl0;
                    g_er[row * HEADS + h0]     = pr0;
                    g_el[row * HEADS + h0 + 1] = pl1;
                    g_er[row * HEADS + h0 + 1] = pr1;
                }
                __half* fr = g_feat_h + row * FEAT + warp_n * 64;
                #pragma unroll
                for (int nt = 0; nt < 8; nt++) {
                    __half2 hv = __floats2half2_rn(d[mt][nt][v * 2], d[mt][nt][v * 2 + 1]);
                    *(__half2*)(fr + nt * 8 + c * 2) = hv;
                }
            }
        }
    }
}

// ---------------- 2) CSR build ------------------------------------------------
// count + rank: the atomic's return value IS the edge's slot within its bucket.
__global__ void count_kernel(const int* __restrict__ dst, int nE) {
    int i4 = (blockIdx.x * blockDim.x + threadIdx.x) * 4;
    if (i4 + 3 < nE) {
        int4 d = *(const int4*)(dst + i4);
        int4 r;
        r.x = atomicAdd(&g_deg[d.x], 1);
        r.y = atomicAdd(&g_deg[d.y], 1);
        r.z = atomicAdd(&g_deg[d.z], 1);
        r.w = atomicAdd(&g_deg[d.w], 1);
        *(int4*)(g_rank + i4) = r;
    } else {
        for (int i = i4; i < nE; i++) g_rank[i] = atomicAdd(&g_deg[dst[i]], 1);
    }
}

// fused exclusive scan: one launch, grid-wide spin barrier (49 blocks, all resident)
__global__ __launch_bounds__(256) void scan_fused() {
    int t = threadIdx.x, b = blockIdx.x;
    int base = b * 1024 + t * 4;
    int4 v = *(const int4*)(g_deg + base);
    int tsum = v.x + v.y + v.z + v.w;
    int lane = t & 31, wid = t >> 5;

    int inc = tsum;
    #pragma unroll
    for (int d = 1; d < 32; d <<= 1) {
        int u = __shfl_up_sync(0xffffffffu, inc, d);
        if (lane >= d) inc += u;
    }
    __shared__ int wtot[8], woff[8], s_total;
    if (lane == 31) wtot[wid] = inc;
    __syncthreads();
    if (t < 8) {
        int xv = wtot[t], p = xv;
        #pragma unroll
        for (int d = 1; d < 8; d <<= 1) {
            int u = __shfl_up_sync(0xffu, p, d, 8);
            if (t >= d) p += u;
        }
        woff[t] = p - xv;
        if (t == 7) s_total = p;
    }
    __syncthreads();

    if (t == 0) {
        g_bsum[b] = s_total;
        __threadfence();
        atomicAdd(&g_deg[N_PAD], 1);
        while (((volatile int*)g_deg)[N_PAD] < SCAN_NB) { }
        __threadfence();
    }
    __syncthreads();

    __shared__ int s_part[2];
    if (t < 64) {
        int pv = (t < SCAN_NB && t < b) ? g_bsum[t] : 0;
        #pragma unroll
        for (int d = 16; d; d >>= 1) pv += __shfl_xor_sync(0xffffffffu, pv, d);
        if ((t & 31) == 0) s_part[t >> 5] = pv;
    }
    __syncthreads();
    const int boff = s_part[0] + s_part[1];

    int pref = boff + woff[wid] + (inc - tsum);
    int4 o;
    o.x = pref;
    o.y = o.x + v.x;
    o.z = o.y + v.y;
    o.w = o.z + v.z;
    *(int4*)(g_off + base) = o;
}

// ---------------- 3) scatter — atomic-free (off gather + precomputed rank) ---
__global__ void scatter_kernel(const int* __restrict__ src,
                               const int* __restrict__ dst, int nE) {
    int i4 = (blockIdx.x * blockDim.x + threadIdx.x) * 4;
    if (i4 + 3 < nE) {
        int4 d = *(const int4*)(dst + i4);
        int4 r = *(const int4*)(g_rank + i4);
        int4 s = *(const int4*)(src + i4);
        g_csr[__ldg(&g_off[d.x]) + r.x] = s.x;
        g_csr[__ldg(&g_off[d.y]) + r.y] = s.y;
        g_csr[__ldg(&g_off[d.z]) + r.z] = s.z;
        g_csr[__ldg(&g_off[d.w]) + r.w] = s.w;
    } else {
        for (int i = i4; i < nE; i++)
            g_csr[__ldg(&g_off[dst[i]]) + g_rank[i]] = src[i];
    }
}

// ---------------- 4) aggregation (half-warp per node, inline edge weights) ---
__global__ __launch_bounds__(256) void aggregate_kernel(const float* __restrict__ bias,
                                                        float* __restrict__ out) {
    int node = (blockIdx.x * blockDim.x + threadIdx.x) >> 4;
    int l    = threadIdx.x & 15;
    if (node >= N_NODES) return;

    int beg = g_off[node], end = g_off[node + 1];
    int hh = l >> 2;

    const float er_h = __ldg(&g_er[node * HEADS + hh]);

    float acc[8];
    #pragma unroll
    for (int j = 0; j < 8; j++) acc[j] = 0.f;
    float s = 0.f;

    for (int i = beg; i < end; i++) {
        int sp = __ldg(&g_csr[i]);
        float e = __ldg(&g_el[sp * HEADS + hh]) + er_h;
        e = e > 0.f ? e : NEG_SLOPE * e;
        float wv = __expf(e);
        float4 raw = *(const float4*)(g_feat_h + (size_t)sp * FEAT + l * 8);
        const __half2* hp = (const __half2*)&raw;
        #pragma unroll
        for (int q = 0; q < 4; q++) {
            float2 f = __half22float2(hp[q]);
            acc[2 * q]     += wv * f.x;
            acc[2 * q + 1] += wv * f.y;
        }
        s += wv;
    }

    float inv = (end > beg) ? (1.0f / s) : 0.0f;
    const float* bp = bias + hh * OUT_CH + (l & 3) * 8;
    #pragma unroll
    for (int j = 0; j < 8; j++) acc[j] = acc[j] * inv + bp[j];

    #pragma unroll
    for (int d = 4; d < 16; d <<= 1)
        #pragma unroll
        for (int j = 0; j < 8; j++)
            acc[j] += __shfl_xor_sync(0xffffffffu, acc[j], d, 16);

    if (l < 4) {
        float4 o0 = make_float4(acc[0] * 0.25f, acc[1] * 0.25f,
                                acc[2] * 0.25f, acc[3] * 0.25f);
        float4 o1 = make_float4(acc[4] * 0.25f, acc[5] * 0.25f,
                                acc[6] * 0.25f, acc[7] * 0.25f);
        *(float4*)(out + node * OUT_CH + l * 8)     = o0;
        *(float4*)(out + node * OUT_CH + l * 8 + 4) = o1;
    }
}

// ---------------- launch ------------------------------------------------------
extern "C" void kernel_launch(void* const* d_in, const int* in_sizes, int n_in,
                              void* d_out, int out_size) {
    const float* x      = (const float*)d_in[0];
    const int*   src    = (const int*)  d_in[1];
    const int*   dst    = (const int*)  d_in[2];
    const float* W      = (const float*)d_in[3];
    const float* attn_l = (const float*)d_in[4];
    const float* attn_r = (const float*)d_in[5];
    const float* bias   = (const float*)d_in[6];
    float*       out    = (float*)d_out;

    const int nE = in_sizes[1];

    // fork: gemm on side stream, fully concurrent with the CSR chain
    cudaEventRecord(g_ev_fork, 0);
    cudaStreamWaitEvent(g_s2, g_ev_fork, 0);
    gemm_kernel<<<(N_NODES + 127) / 128, 256, 0, g_s2>>>(x, W, attn_l, attn_r);
    cudaEventRecord(g_ev_join, g_s2);

    // CSR chain on main stream (memset also resets the scan's arrival counter)
    void* deg_ptr = nullptr;
    cudaGetSymbolAddress(&deg_ptr, g_deg);
    cudaMemsetAsync(deg_ptr, 0, (N_PAD + 4) * sizeof(int), 0);
    count_kernel<<<((nE + 3) / 4 + 255) / 256, 256>>>(dst, nE);
    scan_fused<<<SCAN_NB, 256>>>();
    scatter_kernel<<<((nE + 3) / 4 + 255) / 256, 256>>>(src, dst, nE);

    // join: aggregate needs feat/el/er (gemm) and csr (scatter)
    cudaStreamWaitEvent(0, g_ev_join, 0);
    aggregate_kernel<<<(N_NODES * 16 + 255) / 256, 256>>>(bias, out);
}